// round 1
// baseline (speedup 1.0000x reference)
#include <cuda_runtime.h>
#include <math.h>

// Problem shapes (fixed by the dataset):
//   x  [B=8, S=4096, H=1024]  -> tokens [N=32768, 1024]
//   Wg [1024, 8], bg [8]
//   We [1024, 1024], be [1024]
// out[i][j] = (tokens[i] . We[:,j] + be[j]) * best_p[i]
// best_p[i] = softmax(tokens[i]@Wg + bg)[argmax] = 1 / sum_e exp(l_e - l_max)

#define N_TOKENS (8 * 4096)
#define HDIM 1024
#define NEXP 8

__device__ float g_bestp[N_TOKENS];

// ---------------------------------------------------------------------------
// Router: one warp per token. Each lane strides over H, accumulating the 8
// expert partial dots; warp-reduce via shfl_xor; then best_p closed form.
// ---------------------------------------------------------------------------
__global__ void router_kernel(const float* __restrict__ x,
                              const float* __restrict__ Wg,
                              const float* __restrict__ bg)
{
    int warp = (blockIdx.x * blockDim.x + threadIdx.x) >> 5;
    int lane = threadIdx.x & 31;
    if (warp >= N_TOKENS) return;

    const float* xr = x + (size_t)warp * HDIM;

    float acc[NEXP];
#pragma unroll
    for (int e = 0; e < NEXP; e++) acc[e] = 0.f;

    for (int h = lane; h < HDIM; h += 32) {
        float xv = xr[h];
        const float* wrow = Wg + h * NEXP;
#pragma unroll
        for (int e = 0; e < NEXP; e++) acc[e] += xv * wrow[e];
    }

    // butterfly reduce each of the 8 sums across the warp
#pragma unroll
    for (int e = 0; e < NEXP; e++) {
#pragma unroll
        for (int off = 16; off > 0; off >>= 1)
            acc[e] += __shfl_xor_sync(0xFFFFFFFFu, acc[e], off);
    }

    if (lane == 0) {
        float lmax = -INFINITY;
#pragma unroll
        for (int e = 0; e < NEXP; e++) {
            float l = acc[e] + bg[e];
            acc[e] = l;
            lmax = fmaxf(lmax, l);
        }
        float sum = 0.f;
#pragma unroll
        for (int e = 0; e < NEXP; e++) sum += __expf(acc[e] - lmax);
        g_bestp[warp] = 1.0f / sum;
    }
}

// ---------------------------------------------------------------------------
// SGEMM: C[M,N] = (A[M,K] @ B[K,N] + bias[N]) * p[M]
// BM=BN=128, BK=8, 256 threads, 8x8 micro-tile per thread.
// ---------------------------------------------------------------------------
#define BM 128
#define BN 128
#define BK 8
#define TM 8
#define TN 8

__global__ __launch_bounds__(256, 2)
void gemm_scaled_kernel(const float* __restrict__ A,
                        const float* __restrict__ B,
                        const float* __restrict__ bias,
                        const float* __restrict__ p,
                        float* __restrict__ C,
                        int M, int N, int K)
{
    __shared__ float As[BK][BM];   // A tile, transposed
    __shared__ float Bs[BK][BN];

    int tid = threadIdx.x;
    int bx = blockIdx.x;   // N tile index
    int by = blockIdx.y;   // M tile index

    // A tile loads: 128 rows x 8 cols = 1024 floats = 256 float4
    int arow = tid >> 1;           // 0..127
    int acol = (tid & 1) << 2;     // 0 or 4
    // B tile loads: 8 rows x 128 cols
    int brow = tid >> 5;           // 0..7
    int bcol = (tid & 31) << 2;    // 0..124

    const float* Aptr = A + ((size_t)by * BM + arow) * K;
    const float* Bptr = B + (size_t)bx * BN;

    int trow = (tid >> 4) * TM;    // 0..120
    int tcol = (tid & 15) * TN;    // 0..120

    float acc[TM][TN];
#pragma unroll
    for (int i = 0; i < TM; i++)
#pragma unroll
        for (int j = 0; j < TN; j++) acc[i][j] = 0.f;

    for (int k0 = 0; k0 < K; k0 += BK) {
        float4 av = *reinterpret_cast<const float4*>(Aptr + k0 + acol);
        As[acol + 0][arow] = av.x;
        As[acol + 1][arow] = av.y;
        As[acol + 2][arow] = av.z;
        As[acol + 3][arow] = av.w;

        float4 bv = *reinterpret_cast<const float4*>(Bptr + (size_t)(k0 + brow) * N + bcol);
        *reinterpret_cast<float4*>(&Bs[brow][bcol]) = bv;

        __syncthreads();

#pragma unroll
        for (int k = 0; k < BK; k++) {
            float ar[TM], br[TN];
            float4 a0 = *reinterpret_cast<const float4*>(&As[k][trow]);
            float4 a1 = *reinterpret_cast<const float4*>(&As[k][trow + 4]);
            ar[0]=a0.x; ar[1]=a0.y; ar[2]=a0.z; ar[3]=a0.w;
            ar[4]=a1.x; ar[5]=a1.y; ar[6]=a1.z; ar[7]=a1.w;
            float4 b0 = *reinterpret_cast<const float4*>(&Bs[k][tcol]);
            float4 b1 = *reinterpret_cast<const float4*>(&Bs[k][tcol + 4]);
            br[0]=b0.x; br[1]=b0.y; br[2]=b0.z; br[3]=b0.w;
            br[4]=b1.x; br[5]=b1.y; br[6]=b1.z; br[7]=b1.w;
#pragma unroll
            for (int i = 0; i < TM; i++)
#pragma unroll
                for (int j = 0; j < TN; j++)
                    acc[i][j] += ar[i] * br[j];
        }
        __syncthreads();
    }

    // Epilogue: (acc + bias[col]) * p[row]
#pragma unroll
    for (int i = 0; i < TM; i++) {
        int row = by * BM + trow + i;
        float pv = p[row];
        float* crow = C + (size_t)row * N + bx * BN;
#pragma unroll
        for (int j = 0; j < TN; j += 4) {
            int col = bx * BN + tcol + j;
            float4 o;
            o.x = (acc[i][j + 0] + bias[col + 0]) * pv;
            o.y = (acc[i][j + 1] + bias[col + 1]) * pv;
            o.z = (acc[i][j + 2] + bias[col + 2]) * pv;
            o.w = (acc[i][j + 3] + bias[col + 3]) * pv;
            *reinterpret_cast<float4*>(crow + tcol + j) = o;
        }
    }
}

extern "C" void kernel_launch(void* const* d_in, const int* in_sizes, int n_in,
                              void* d_out, int out_size)
{
    const float* x  = (const float*)d_in[0];
    const float* Wg = (const float*)d_in[1];
    const float* bg = (const float*)d_in[2];
    const float* We = (const float*)d_in[3];
    const float* be = (const float*)d_in[4];
    float* out = (float*)d_out;

    float* bestp;
    cudaGetSymbolAddress((void**)&bestp, g_bestp);

    // Router: 1 warp/token, 8 warps/block
    {
        int threads = 256;
        int warps_per_block = threads / 32;
        int blocks = (N_TOKENS + warps_per_block - 1) / warps_per_block;
        router_kernel<<<blocks, threads>>>(x, Wg, bg);
    }

    // Main GEMM: M=32768, N=1024, K=1024
    {
        dim3 grid(HDIM / BN, N_TOKENS / BM);  // (8, 256)
        gemm_scaled_kernel<<<grid, 256>>>(x, We, be, bestp, out,
                                          N_TOKENS, HDIM, HDIM);
    }
}

// round 9
// speedup vs baseline: 1.1514x; 1.1514x over previous
#include <cuda_runtime.h>
#include <cuda_bf16.h>
#include <cstdint>
#include <math.h>

// Shapes fixed by dataset:
//   x [8,4096,1024] -> tokens [N=32768, H=1024]
//   Wg [1024,8], bg[8], We [1024,1024], be[1024]
// out[i][j] = (tokens[i] . We[:,j] + be[j]) * best_p[i]
// best_p[i] = 1 / sum_e exp(l_e - l_max)

#define N_TOKENS 32768
#define HDIM 1024
#define NEXP 8

// ---------------- scratch (static device globals; 1KB aligned) -------------
__device__ __align__(1024) float         g_bestp[N_TOKENS];
__device__ __align__(1024) __nv_bfloat16 g_xhi[(size_t)N_TOKENS * HDIM];
__device__ __align__(1024) __nv_bfloat16 g_xlo[(size_t)N_TOKENS * HDIM];
__device__ __align__(1024) __nv_bfloat16 g_wthi[(size_t)HDIM * HDIM];   // We^T [n][k]
__device__ __align__(1024) __nv_bfloat16 g_wtlo[(size_t)HDIM * HDIM];

// ---------------- helpers ---------------------------------------------------
__device__ __forceinline__ uint32_t smem_u32(const void* p) {
    uint32_t a;
    asm("{ .reg .u64 t; cvta.to.shared.u64 t, %1; cvt.u32.u64 %0, t; }"
        : "=r"(a) : "l"(p));
    return a;
}

__device__ __forceinline__ void cp16(uint32_t dst, const void* src) {
    asm volatile("cp.async.cg.shared.global [%0], [%1], 16;"
                 :: "r"(dst), "l"(src));
}

__device__ __forceinline__ void ldmatrix_x4(uint32_t* r, uint32_t addr) {
    asm volatile("ldmatrix.sync.aligned.m8n8.x4.shared.b16 {%0,%1,%2,%3}, [%4];"
                 : "=r"(r[0]), "=r"(r[1]), "=r"(r[2]), "=r"(r[3]) : "r"(addr));
}

__device__ __forceinline__ void mma_bf16(float* d, const uint32_t* a,
                                         const uint32_t* b) {
    asm volatile(
        "mma.sync.aligned.m16n8k16.row.col.f32.bf16.bf16.f32 "
        "{%0,%1,%2,%3}, {%4,%5,%6,%7}, {%8,%9}, {%0,%1,%2,%3};"
        : "+f"(d[0]), "+f"(d[1]), "+f"(d[2]), "+f"(d[3])
        : "r"(a[0]), "r"(a[1]), "r"(a[2]), "r"(a[3]), "r"(b[0]), "r"(b[1]));
}

// ---------------- prep: router + x -> bf16 hi/lo ---------------------------
__global__ void __launch_bounds__(256)
prep_kernel(const float* __restrict__ x, const float* __restrict__ Wg,
            const float* __restrict__ bg,
            __nv_bfloat16* __restrict__ xhi, __nv_bfloat16* __restrict__ xlo,
            float* __restrict__ bestp)
{
    __shared__ float red[8][NEXP];
    int token = blockIdx.x;
    int t = threadIdx.x, lane = t & 31, wid = t >> 5;

    float4 v4 = reinterpret_cast<const float4*>(x + (size_t)token * HDIM)[t];
    float v[4] = {v4.x, v4.y, v4.z, v4.w};

    uint32_t hp[2], lp[2];
#pragma unroll
    for (int i = 0; i < 2; i++) {
        __nv_bfloat16 h0 = __float2bfloat16_rn(v[2*i]);
        __nv_bfloat16 h1 = __float2bfloat16_rn(v[2*i+1]);
        __nv_bfloat16 l0 = __float2bfloat16_rn(v[2*i]   - __bfloat162float(h0));
        __nv_bfloat16 l1 = __float2bfloat16_rn(v[2*i+1] - __bfloat162float(h1));
        hp[i] = (uint32_t)__bfloat16_as_ushort(h0) |
                ((uint32_t)__bfloat16_as_ushort(h1) << 16);
        lp[i] = (uint32_t)__bfloat16_as_ushort(l0) |
                ((uint32_t)__bfloat16_as_ushort(l1) << 16);
    }
    size_t off = (size_t)token * HDIM + t * 4;
    *reinterpret_cast<uint2*>(xhi + off) = make_uint2(hp[0], hp[1]);
    *reinterpret_cast<uint2*>(xlo + off) = make_uint2(lp[0], lp[1]);

    float acc[NEXP];
#pragma unroll
    for (int e = 0; e < NEXP; e++) acc[e] = 0.f;
    const float* wg = Wg + (size_t)t * 4 * NEXP;
#pragma unroll
    for (int i = 0; i < 4; i++)
#pragma unroll
        for (int e = 0; e < NEXP; e++) acc[e] += v[i] * wg[i * NEXP + e];

#pragma unroll
    for (int e = 0; e < NEXP; e++)
#pragma unroll
        for (int o = 16; o > 0; o >>= 1)
            acc[e] += __shfl_xor_sync(0xFFFFFFFFu, acc[e], o);

    if (lane == 0)
#pragma unroll
        for (int e = 0; e < NEXP; e++) red[wid][e] = acc[e];
    __syncthreads();

    if (t == 0) {
        float lg[NEXP], lmax = -INFINITY;
#pragma unroll
        for (int e = 0; e < NEXP; e++) {
            float s = bg[e];
#pragma unroll
            for (int w = 0; w < 8; w++) s += red[w][e];
            lg[e] = s;
            lmax = fmaxf(lmax, s);
        }
        float sum = 0.f;
#pragma unroll
        for (int e = 0; e < NEXP; e++) sum += __expf(lg[e] - lmax);
        bestp[token] = 1.0f / sum;
    }
}

// ---------------- We transpose + hi/lo split -------------------------------
__global__ void __launch_bounds__(256)
convert_w_kernel(const float* __restrict__ We,
                 __nv_bfloat16* __restrict__ wthi,
                 __nv_bfloat16* __restrict__ wtlo)
{
    __shared__ float tile[32][33];
    int bx = blockIdx.x, by = blockIdx.y;     // bx: n tile, by: k tile
    int tx = threadIdx.x & 31, ty = threadIdx.x >> 5;
#pragma unroll
    for (int j = 0; j < 4; j++)
        tile[ty + 8 * j][tx] = We[(size_t)(by * 32 + ty + 8 * j) * HDIM + bx * 32 + tx];
    __syncthreads();
#pragma unroll
    for (int j = 0; j < 4; j++) {
        int n = bx * 32 + ty + 8 * j;
        int k = by * 32 + tx;
        float v = tile[tx][ty + 8 * j];
        __nv_bfloat16 h = __float2bfloat16_rn(v);
        __nv_bfloat16 l = __float2bfloat16_rn(v - __bfloat162float(h));
        wthi[(size_t)n * HDIM + k] = h;
        wtlo[(size_t)n * HDIM + k] = l;
    }
}

// ---------------- HMMA GEMM -------------------------------------------------
// C[M,N] = (Ahi@Bhi^T + Ahi@Blo^T + Alo@Bhi^T + bias) * p
// Flat K = 3*1024, BK=32 -> 96 chunks; phase = chunk/32 selects (A,B) source.
#define BM 128
#define BN 128
#define BK 32
#define NCH 96
#define ROWB 80                       // padded smem row stride (bytes)
#define STAGE_A_BYTES (BM * ROWB)     // 10240
#define STAGE_BYTES   (2 * STAGE_A_BYTES)
#define STAGES 3
#define SMEM_TOTAL (STAGES * STAGE_BYTES)   // 61440

__device__ __forceinline__ void load_chunk(
    uint32_t stage, const __nv_bfloat16* __restrict__ a_src,
    const __nv_bfloat16* __restrict__ b_src,
    int by, int bx, int k0, int tid)
{
    // A: 128 rows x 64B = 512 x 16B; 2 per thread. Same for B.
#pragma unroll
    for (int t = 0; t < 2; t++) {
        int idx = tid + t * 256;
        int row = idx >> 2, c = idx & 3;
        cp16(stage + row * ROWB + c * 16,
             a_src + (size_t)(by * BM + row) * HDIM + k0 + c * 8);
    }
#pragma unroll
    for (int t = 0; t < 2; t++) {
        int idx = tid + t * 256;
        int row = idx >> 2, c = idx & 3;
        cp16(stage + STAGE_A_BYTES + row * ROWB + c * 16,
             b_src + (size_t)(bx * BN + row) * HDIM + k0 + c * 8);
    }
}

__global__ void __launch_bounds__(256, 2)
moe_mma_kernel(const __nv_bfloat16* __restrict__ xhi,
               const __nv_bfloat16* __restrict__ xlo,
               const __nv_bfloat16* __restrict__ wthi,
               const __nv_bfloat16* __restrict__ wtlo,
               const float* __restrict__ bias,
               const float* __restrict__ p,
               float* __restrict__ C)
{
    extern __shared__ char smem[];
    uint32_t sb = smem_u32(smem);
    int tid = threadIdx.x, lane = tid & 31, wid = tid >> 5;
    int wm = wid & 1, wn = wid >> 1;          // warp grid 2 x 4
    int bx = blockIdx.x, by = blockIdx.y;

    const __nv_bfloat16* aphase[3] = {xhi, xhi, xlo};
    const __nv_bfloat16* bphase[3] = {wthi, wtlo, wthi};

    float acc[4][4][4];
#pragma unroll
    for (int i = 0; i < 4; i++)
#pragma unroll
        for (int j = 0; j < 4; j++)
#pragma unroll
            for (int r = 0; r < 4; r++) acc[i][j][r] = 0.f;

    // prologue: chunks 0,1
    load_chunk(sb, aphase[0], bphase[0], by, bx, 0, tid);
    asm volatile("cp.async.commit_group;" ::: "memory");
    load_chunk(sb + STAGE_BYTES, aphase[0], bphase[0], by, bx, BK, tid);
    asm volatile("cp.async.commit_group;" ::: "memory");

    // per-warp ldmatrix base offsets (within a stage)
    // A: row = wm*64 + mi*16 + (lane&15), 16B chunk = lane>>4
    uint32_t a_off = (uint32_t)((wm * 64 + (lane & 15)) * ROWB + (lane >> 4) * 16);
    // B (x4 covers two n-tiles): group g = lane>>3: row = wn*32 + (g>>1)*8 + (lane&7),
    // chunk = g&1
    int g = lane >> 3;
    uint32_t b_off = (uint32_t)(STAGE_A_BYTES +
                     (wn * 32 + (g >> 1) * 8 + (lane & 7)) * ROWB + (g & 1) * 16);

    for (int c = 0; c < NCH; c++) {
        if (c + 2 < NCH)
            asm volatile("cp.async.wait_group 1;" ::: "memory");
        else
            asm volatile("cp.async.wait_group 0;" ::: "memory");
        __syncthreads();

        if (c + 2 < NCH) {
            int nc = c + 2, ph = nc >> 5, k0 = (nc & 31) * BK;
            load_chunk(sb + (nc % 3) * STAGE_BYTES, aphase[ph], bphase[ph],
                       by, bx, k0, tid);
            asm volatile("cp.async.commit_group;" ::: "memory");
        }

        uint32_t stage = sb + (c % 3) * STAGE_BYTES;
#pragma unroll
        for (int ks = 0; ks < 2; ks++) {
            uint32_t af[4][4], bf[2][4];
#pragma unroll
            for (int mi = 0; mi < 4; mi++)
                ldmatrix_x4(af[mi], stage + a_off + mi * 16 * ROWB + ks * 32);
#pragma unroll
            for (int np = 0; np < 2; np++)
                ldmatrix_x4(bf[np], stage + b_off + np * 16 * ROWB + ks * 32);
#pragma unroll
            for (int mi = 0; mi < 4; mi++) {
#pragma unroll
                for (int ni = 0; ni < 4; ni++)
                    mma_bf16(acc[mi][ni], af[mi], &bf[ni >> 1][(ni & 1) * 2]);
            }
        }
    }

    // epilogue: (acc + bias) * p
    int m0 = by * BM + wm * 64;
    int n0 = bx * BN + wn * 32;
#pragma unroll
    for (int mi = 0; mi < 4; mi++) {
        int r0 = m0 + mi * 16 + (lane >> 2);
        int r1 = r0 + 8;
        float p0 = p[r0], p1 = p[r1];
#pragma unroll
        for (int ni = 0; ni < 4; ni++) {
            int n = n0 + ni * 8 + (lane & 3) * 2;
            float b0 = bias[n], b1 = bias[n + 1];
            float2 o0 = make_float2((acc[mi][ni][0] + b0) * p0,
                                    (acc[mi][ni][1] + b1) * p0);
            float2 o1 = make_float2((acc[mi][ni][2] + b0) * p1,
                                    (acc[mi][ni][3] + b1) * p1);
            *reinterpret_cast<float2*>(C + (size_t)r0 * HDIM + n) = o0;
            *reinterpret_cast<float2*>(C + (size_t)r1 * HDIM + n) = o1;
        }
    }
}

// ---------------- launch ----------------------------------------------------
extern "C" void kernel_launch(void* const* d_in, const int* in_sizes, int n_in,
                              void* d_out, int out_size)
{
    const float* x  = (const float*)d_in[0];
    const float* Wg = (const float*)d_in[1];
    const float* bg = (const float*)d_in[2];
    const float* We = (const float*)d_in[3];
    const float* be = (const float*)d_in[4];
    float* out = (float*)d_out;

    float* bestp;        cudaGetSymbolAddress((void**)&bestp, g_bestp);
    __nv_bfloat16* xhi;  cudaGetSymbolAddress((void**)&xhi, g_xhi);
    __nv_bfloat16* xlo;  cudaGetSymbolAddress((void**)&xlo, g_xlo);
    __nv_bfloat16* wthi; cudaGetSymbolAddress((void**)&wthi, g_wthi);
    __nv_bfloat16* wtlo; cudaGetSymbolAddress((void**)&wtlo, g_wtlo);

    cudaFuncSetAttribute(moe_mma_kernel,
                         cudaFuncAttributeMaxDynamicSharedMemorySize, SMEM_TOTAL);

    prep_kernel<<<N_TOKENS, 256>>>(x, Wg, bg, xhi, xlo, bestp);
    convert_w_kernel<<<dim3(32, 32), 256>>>(We, wthi, wtlo);

    dim3 grid(HDIM / BN, N_TOKENS / BM);   // (8, 256)
    moe_mma_kernel<<<grid, 256, SMEM_TOTAL>>>(xhi, xlo, wthi, wtlo, be, bestp, out);
}

// round 11
// speedup vs baseline: 3.2019x; 2.7808x over previous
#include <cuda_runtime.h>
#include <cuda_fp16.h>
#include <cstdint>
#include <math.h>

// Shapes fixed by dataset:
//   x [8,4096,1024] -> tokens [N=32768, H=1024]
//   Wg [1024,8], bg[8], We [1024,1024], be[1024]
// out[i][j] = (tokens[i] . We[:,j] + be[j]) * best_p[i]
// best_p[i] = 1 / sum_e exp(l_e - l_max)

#define N_TOKENS 32768
#define HDIM 1024
#define NEXP 8

// ---------------- scratch (static device globals; 1KB aligned) -------------
__device__ __align__(1024) float  g_bestp[N_TOKENS];
__device__ __align__(1024) __half g_xh[(size_t)N_TOKENS * HDIM];
__device__ __align__(1024) __half g_wt[(size_t)HDIM * HDIM];   // We^T [n][k], fp16

// ---------------- helpers ---------------------------------------------------
__device__ __forceinline__ uint32_t smem_u32(const void* p) {
    uint32_t a;
    asm("{ .reg .u64 t; cvta.to.shared.u64 t, %1; cvt.u32.u64 %0, t; }"
        : "=r"(a) : "l"(p));
    return a;
}

__device__ __forceinline__ void cp16(uint32_t dst, const void* src) {
    asm volatile("cp.async.cg.shared.global [%0], [%1], 16;"
                 :: "r"(dst), "l"(src));
}

__device__ __forceinline__ void ldmatrix_x4(uint32_t* r, uint32_t addr) {
    asm volatile("ldmatrix.sync.aligned.m8n8.x4.shared.b16 {%0,%1,%2,%3}, [%4];"
                 : "=r"(r[0]), "=r"(r[1]), "=r"(r[2]), "=r"(r[3]) : "r"(addr));
}

__device__ __forceinline__ void mma_fp16(float* d, const uint32_t* a,
                                         const uint32_t* b) {
    asm volatile(
        "mma.sync.aligned.m16n8k16.row.col.f32.f16.f16.f32 "
        "{%0,%1,%2,%3}, {%4,%5,%6,%7}, {%8,%9}, {%0,%1,%2,%3};"
        : "+f"(d[0]), "+f"(d[1]), "+f"(d[2]), "+f"(d[3])
        : "r"(a[0]), "r"(a[1]), "r"(a[2]), "r"(a[3]), "r"(b[0]), "r"(b[1]));
}

// ---------------- prep: router + x -> fp16 ---------------------------------
// 256 threads per block, 128 tokens per block. Per-thread Wg slice (rows
// 4t..4t+3, all 8 experts = 32 floats) loaded ONCE per block into registers.
#define TPB 128

__global__ void __launch_bounds__(256)
prep_kernel(const float* __restrict__ x, const float* __restrict__ Wg,
            const float* __restrict__ bg,
            __half* __restrict__ xh, float* __restrict__ bestp)
{
    __shared__ float red[8][NEXP];
    int t = threadIdx.x, lane = t & 31, wid = t >> 5;

    // per-thread router weights (amortized over TPB tokens; L1/L2 resident)
    float wreg[4][NEXP];
#pragma unroll
    for (int i = 0; i < 4; i++)
#pragma unroll
        for (int e = 0; e < NEXP; e++)
            wreg[i][e] = Wg[(size_t)(t * 4 + i) * NEXP + e];

    int tok0 = blockIdx.x * TPB;
    for (int tk = 0; tk < TPB; tk++) {
        int token = tok0 + tk;
        float4 v4 = reinterpret_cast<const float4*>(x + (size_t)token * HDIM)[t];
        float v[4] = {v4.x, v4.y, v4.z, v4.w};

        // fp16 convert + coalesced 8B store
        __half2 h0 = __floats2half2_rn(v4.x, v4.y);
        __half2 h1 = __floats2half2_rn(v4.z, v4.w);
        uint2 st;
        st.x = *reinterpret_cast<uint32_t*>(&h0);
        st.y = *reinterpret_cast<uint32_t*>(&h1);
        *reinterpret_cast<uint2*>(xh + (size_t)token * HDIM + t * 4) = st;

        // router partial dots
        float acc[NEXP];
#pragma unroll
        for (int e = 0; e < NEXP; e++) acc[e] = 0.f;
#pragma unroll
        for (int i = 0; i < 4; i++)
#pragma unroll
            for (int e = 0; e < NEXP; e++) acc[e] += v[i] * wreg[i][e];

#pragma unroll
        for (int e = 0; e < NEXP; e++)
#pragma unroll
            for (int o = 16; o > 0; o >>= 1)
                acc[e] += __shfl_xor_sync(0xFFFFFFFFu, acc[e], o);

        if (lane == 0)
#pragma unroll
            for (int e = 0; e < NEXP; e++) red[wid][e] = acc[e];
        __syncthreads();

        if (wid == 0 && lane < NEXP) {
            float s = bg[lane];
#pragma unroll
            for (int w = 0; w < 8; w++) s += red[w][lane];
            float m = s;
#pragma unroll
            for (int o = 4; o > 0; o >>= 1)
                m = fmaxf(m, __shfl_xor_sync(0xFFu, m, o, 8));
            float ex = __expf(s - m);
#pragma unroll
            for (int o = 4; o > 0; o >>= 1)
                ex += __shfl_xor_sync(0xFFu, ex, o, 8);
            if (lane == 0) bestp[token] = 1.0f / ex;
        }
        __syncthreads();
    }
}

// ---------------- We transpose -> fp16 WeT[n][k] ---------------------------
__global__ void __launch_bounds__(256)
convert_w_kernel(const float* __restrict__ We, __half* __restrict__ wt)
{
    __shared__ float tile[32][33];
    int bx = blockIdx.x, by = blockIdx.y;     // bx: n tile, by: k tile
    int tx = threadIdx.x & 31, ty = threadIdx.x >> 5;
#pragma unroll
    for (int j = 0; j < 4; j++)
        tile[ty + 8 * j][tx] = We[(size_t)(by * 32 + ty + 8 * j) * HDIM + bx * 32 + tx];
    __syncthreads();
#pragma unroll
    for (int j = 0; j < 4; j++) {
        int n = bx * 32 + ty + 8 * j;
        int k = by * 32 + tx;
        wt[(size_t)n * HDIM + k] = __float2half_rn(tile[tx][ty + 8 * j]);
    }
}

// ---------------- HMMA GEMM (single fp16 product) --------------------------
// C[M,N] = (Xh@WeT^T + bias) * p ; K = 1024, BK=64 -> 16 chunks, 3 stages.
#define BM 128
#define BN 128
#define BK 64
#define NCH (HDIM / BK)               // 16
#define ROWB 144                      // 128B data + 16B pad (4 banks mod 32)
#define STAGE_A_BYTES (BM * ROWB)     // 18432
#define STAGE_BYTES   (2 * STAGE_A_BYTES)
#define STAGES 3
#define SMEM_TOTAL (STAGES * STAGE_BYTES)   // 110592

__device__ __forceinline__ void load_chunk(
    uint32_t stage, const __half* __restrict__ a_src,
    const __half* __restrict__ b_src,
    int by, int bx, int k0, int tid)
{
    // A: 128 rows x 128B = 1024 x 16B; 4 per thread. Same for B.
#pragma unroll
    for (int t = 0; t < 4; t++) {
        int idx = tid + t * 256;
        int row = idx >> 3, c = idx & 7;
        cp16(stage + row * ROWB + c * 16,
             a_src + (size_t)(by * BM + row) * HDIM + k0 + c * 8);
    }
#pragma unroll
    for (int t = 0; t < 4; t++) {
        int idx = tid + t * 256;
        int row = idx >> 3, c = idx & 7;
        cp16(stage + STAGE_A_BYTES + row * ROWB + c * 16,
             b_src + (size_t)(bx * BN + row) * HDIM + k0 + c * 8);
    }
}

__global__ void __launch_bounds__(256, 2)
moe_mma_kernel(const __half* __restrict__ xh,
               const __half* __restrict__ wt,
               const float* __restrict__ bias,
               const float* __restrict__ p,
               float* __restrict__ C)
{
    extern __shared__ char smem[];
    uint32_t sb = smem_u32(smem);
    int tid = threadIdx.x, lane = tid & 31, wid = tid >> 5;
    int wm = wid & 1, wn = wid >> 1;          // warp grid 2 x 4
    int bx = blockIdx.x, by = blockIdx.y;

    float acc[4][4][4];
#pragma unroll
    for (int i = 0; i < 4; i++)
#pragma unroll
        for (int j = 0; j < 4; j++)
#pragma unroll
            for (int r = 0; r < 4; r++) acc[i][j][r] = 0.f;

    // prologue: chunks 0,1
    load_chunk(sb, xh, wt, by, bx, 0, tid);
    asm volatile("cp.async.commit_group;" ::: "memory");
    load_chunk(sb + STAGE_BYTES, xh, wt, by, bx, BK, tid);
    asm volatile("cp.async.commit_group;" ::: "memory");

    // per-warp ldmatrix base offsets (within a stage)
    uint32_t a_off = (uint32_t)((wm * 64 + (lane & 15)) * ROWB + (lane >> 4) * 16);
    int g = lane >> 3;
    uint32_t b_off = (uint32_t)(STAGE_A_BYTES +
                     (wn * 32 + (g >> 1) * 8 + (lane & 7)) * ROWB + (g & 1) * 16);

    for (int c = 0; c < NCH; c++) {
        if (c + 2 < NCH)
            asm volatile("cp.async.wait_group 1;" ::: "memory");
        else
            asm volatile("cp.async.wait_group 0;" ::: "memory");
        __syncthreads();

        if (c + 2 < NCH) {
            load_chunk(sb + ((c + 2) % 3) * STAGE_BYTES, xh, wt,
                       by, bx, (c + 2) * BK, tid);
            asm volatile("cp.async.commit_group;" ::: "memory");
        }

        uint32_t stage = sb + (c % 3) * STAGE_BYTES;
#pragma unroll
        for (int ks = 0; ks < 4; ks++) {      // 4 K16 steps per BK=64
            uint32_t af[4][4], bf[2][4];
#pragma unroll
            for (int mi = 0; mi < 4; mi++)
                ldmatrix_x4(af[mi], stage + a_off + mi * 16 * ROWB + ks * 32);
#pragma unroll
            for (int np = 0; np < 2; np++)
                ldmatrix_x4(bf[np], stage + b_off + np * 16 * ROWB + ks * 32);
#pragma unroll
            for (int mi = 0; mi < 4; mi++) {
#pragma unroll
                for (int ni = 0; ni < 4; ni++)
                    mma_fp16(acc[mi][ni], af[mi], &bf[ni >> 1][(ni & 1) * 2]);
            }
        }
    }

    // epilogue: (acc + bias) * p
    int m0 = by * BM + wm * 64;
    int n0 = bx * BN + wn * 32;
#pragma unroll
    for (int mi = 0; mi < 4; mi++) {
        int r0 = m0 + mi * 16 + (lane >> 2);
        int r1 = r0 + 8;
        float p0 = p[r0], p1 = p[r1];
#pragma unroll
        for (int ni = 0; ni < 4; ni++) {
            int n = n0 + ni * 8 + (lane & 3) * 2;
            float b0 = bias[n], b1 = bias[n + 1];
            float2 o0 = make_float2((acc[mi][ni][0] + b0) * p0,
                                    (acc[mi][ni][1] + b1) * p0);
            float2 o1 = make_float2((acc[mi][ni][2] + b0) * p1,
                                    (acc[mi][ni][3] + b1) * p1);
            *reinterpret_cast<float2*>(C + (size_t)r0 * HDIM + n) = o0;
            *reinterpret_cast<float2*>(C + (size_t)r1 * HDIM + n) = o1;
        }
    }
}

// ---------------- launch ----------------------------------------------------
extern "C" void kernel_launch(void* const* d_in, const int* in_sizes, int n_in,
                              void* d_out, int out_size)
{
    const float* x  = (const float*)d_in[0];
    const float* Wg = (const float*)d_in[1];
    const float* bg = (const float*)d_in[2];
    const float* We = (const float*)d_in[3];
    const float* be = (const float*)d_in[4];
    float* out = (float*)d_out;

    float* bestp;  cudaGetSymbolAddress((void**)&bestp, g_bestp);
    __half* xh;    cudaGetSymbolAddress((void**)&xh, g_xh);
    __half* wtp;   cudaGetSymbolAddress((void**)&wtp, g_wt);

    cudaFuncSetAttribute(moe_mma_kernel,
                         cudaFuncAttributeMaxDynamicSharedMemorySize, SMEM_TOTAL);

    prep_kernel<<<N_TOKENS / TPB, 256>>>(x, Wg, bg, xh, bestp);
    convert_w_kernel<<<dim3(32, 32), 256>>>(We, wtp);

    dim3 grid(HDIM / BN, N_TOKENS / BM);   // (8, 256)
    moe_mma_kernel<<<grid, 256, SMEM_TOTAL>>>(xh, wtp, be, bestp, out);
}

// round 12
// speedup vs baseline: 5.9239x; 1.8501x over previous
#include <cuda_runtime.h>
#include <cuda_fp16.h>
#include <cstdint>
#include <math.h>

// Shapes fixed by dataset:
//   x [8,4096,1024] -> tokens [N=32768, H=1024]
//   Wg [1024,8], bg[8], We [1024,1024], be[1024]
// out[i][j] = (tokens[i] . We[:,j] + be[j]) * best_p[i]
// best_p[i] = 1 / sum_e exp(l_e - l_max)

#define N_TOKENS 32768
#define HDIM 1024
#define NEXP 8

// ---------------- scratch (static device globals; 1KB aligned) -------------
__device__ __align__(1024) float  g_bestp[N_TOKENS];
__device__ __align__(1024) __half g_xh[(size_t)N_TOKENS * HDIM];
__device__ __align__(1024) __half g_wt[(size_t)HDIM * HDIM];   // We^T [n][k], fp16

// ---------------- helpers ---------------------------------------------------
__device__ __forceinline__ uint32_t smem_u32(const void* p) {
    uint32_t a;
    asm("{ .reg .u64 t; cvta.to.shared.u64 t, %1; cvt.u32.u64 %0, t; }"
        : "=r"(a) : "l"(p));
    return a;
}

__device__ __forceinline__ void cp16(uint32_t dst, const void* src) {
    asm volatile("cp.async.cg.shared.global [%0], [%1], 16;"
                 :: "r"(dst), "l"(src));
}

__device__ __forceinline__ void ldmatrix_x4(uint32_t* r, uint32_t addr) {
    asm volatile("ldmatrix.sync.aligned.m8n8.x4.shared.b16 {%0,%1,%2,%3}, [%4];"
                 : "=r"(r[0]), "=r"(r[1]), "=r"(r[2]), "=r"(r[3]) : "r"(addr));
}

__device__ __forceinline__ void mma_fp16(float* d, const uint32_t* a,
                                         const uint32_t* b) {
    asm volatile(
        "mma.sync.aligned.m16n8k16.row.col.f32.f16.f16.f32 "
        "{%0,%1,%2,%3}, {%4,%5,%6,%7}, {%8,%9}, {%0,%1,%2,%3};"
        : "+f"(d[0]), "+f"(d[1]), "+f"(d[2]), "+f"(d[3])
        : "r"(a[0]), "r"(a[1]), "r"(a[2]), "r"(a[3]), "r"(b[0]), "r"(b[1]));
}

// ---------------- prep: router + x -> fp16 ---------------------------------
// 256 threads per block, TPB tokens per block. Per-thread Wg slice (rows
// 4t..4t+3, all 8 experts = 32 floats) cached in registers once per block.
// Single __syncthreads per token via double-buffered reduction scratch.
#define TPB 16

__global__ void __launch_bounds__(256)
prep_kernel(const float* __restrict__ x, const float* __restrict__ Wg,
            const float* __restrict__ bg,
            __half* __restrict__ xh, float* __restrict__ bestp)
{
    __shared__ float red[2][8][NEXP];
    int t = threadIdx.x, lane = t & 31, wid = t >> 5;

    // per-thread router weights (rows 4t..4t+3 x 8 experts = 128B contiguous)
    float wreg[4][NEXP];
#pragma unroll
    for (int i = 0; i < 4; i++) {
        float4 w0 = *reinterpret_cast<const float4*>(Wg + (size_t)(t * 4 + i) * NEXP);
        float4 w1 = *reinterpret_cast<const float4*>(Wg + (size_t)(t * 4 + i) * NEXP + 4);
        wreg[i][0] = w0.x; wreg[i][1] = w0.y; wreg[i][2] = w0.z; wreg[i][3] = w0.w;
        wreg[i][4] = w1.x; wreg[i][5] = w1.y; wreg[i][6] = w1.z; wreg[i][7] = w1.w;
    }

    int tok0 = blockIdx.x * TPB;
#pragma unroll 1
    for (int tk = 0; tk < TPB; tk++) {
        int token = tok0 + tk;
        int buf = tk & 1;
        float4 v4 = reinterpret_cast<const float4*>(x + (size_t)token * HDIM)[t];
        float v[4] = {v4.x, v4.y, v4.z, v4.w};

        // fp16 convert + coalesced 8B store
        __half2 h0 = __floats2half2_rn(v4.x, v4.y);
        __half2 h1 = __floats2half2_rn(v4.z, v4.w);
        uint2 st;
        st.x = *reinterpret_cast<uint32_t*>(&h0);
        st.y = *reinterpret_cast<uint32_t*>(&h1);
        *reinterpret_cast<uint2*>(xh + (size_t)token * HDIM + t * 4) = st;

        // router partial dots
        float acc[NEXP];
#pragma unroll
        for (int e = 0; e < NEXP; e++) acc[e] = 0.f;
#pragma unroll
        for (int i = 0; i < 4; i++)
#pragma unroll
            for (int e = 0; e < NEXP; e++) acc[e] += v[i] * wreg[i][e];

#pragma unroll
        for (int e = 0; e < NEXP; e++)
#pragma unroll
            for (int o = 16; o > 0; o >>= 1)
                acc[e] += __shfl_xor_sync(0xFFFFFFFFu, acc[e], o);

        if (lane == 0)
#pragma unroll
            for (int e = 0; e < NEXP; e++) red[buf][wid][e] = acc[e];
        __syncthreads();

        // warp 0 finishes this token while others proceed to the next
        // (they write the other red buffer, so no hazard).
        if (wid == 0 && lane < NEXP) {
            float s = bg[lane];
#pragma unroll
            for (int w = 0; w < 8; w++) s += red[buf][w][lane];
            float m = s;
#pragma unroll
            for (int o = 4; o > 0; o >>= 1)
                m = fmaxf(m, __shfl_xor_sync(0xFFu, m, o, 8));
            float ex = __expf(s - m);
#pragma unroll
            for (int o = 4; o > 0; o >>= 1)
                ex += __shfl_xor_sync(0xFFu, ex, o, 8);
            if (lane == 0) bestp[token] = 1.0f / ex;
        }
    }
}

// ---------------- We transpose -> fp16 WeT[n][k] ---------------------------
__global__ void __launch_bounds__(256)
convert_w_kernel(const float* __restrict__ We, __half* __restrict__ wt)
{
    __shared__ float tile[32][33];
    int bx = blockIdx.x, by = blockIdx.y;     // bx: n tile, by: k tile
    int tx = threadIdx.x & 31, ty = threadIdx.x >> 5;
#pragma unroll
    for (int j = 0; j < 4; j++)
        tile[ty + 8 * j][tx] = We[(size_t)(by * 32 + ty + 8 * j) * HDIM + bx * 32 + tx];
    __syncthreads();
#pragma unroll
    for (int j = 0; j < 4; j++) {
        int n = bx * 32 + ty + 8 * j;
        int k = by * 32 + tx;
        wt[(size_t)n * HDIM + k] = __float2half_rn(tile[tx][ty + 8 * j]);
    }
}

// ---------------- HMMA GEMM (single fp16 product) --------------------------
// C[M,N] = (Xh@WeT^T + bias) * p ; K = 1024, BK=64 -> 16 chunks, 3 stages.
#define BM 128
#define BN 128
#define BK 64
#define NCH (HDIM / BK)               // 16
#define ROWB 144                      // 128B data + 16B pad (4 banks mod 32)
#define STAGE_A_BYTES (BM * ROWB)     // 18432
#define STAGE_BYTES   (2 * STAGE_A_BYTES)
#define STAGES 3
#define SMEM_TOTAL (STAGES * STAGE_BYTES)   // 110592

__device__ __forceinline__ void load_chunk(
    uint32_t stage, const __half* __restrict__ a_src,
    const __half* __restrict__ b_src,
    int by, int bx, int k0, int tid)
{
#pragma unroll
    for (int t = 0; t < 4; t++) {
        int idx = tid + t * 256;
        int row = idx >> 3, c = idx & 7;
        cp16(stage + row * ROWB + c * 16,
             a_src + (size_t)(by * BM + row) * HDIM + k0 + c * 8);
    }
#pragma unroll
    for (int t = 0; t < 4; t++) {
        int idx = tid + t * 256;
        int row = idx >> 3, c = idx & 7;
        cp16(stage + STAGE_A_BYTES + row * ROWB + c * 16,
             b_src + (size_t)(bx * BN + row) * HDIM + k0 + c * 8);
    }
}

__global__ void __launch_bounds__(256, 2)
moe_mma_kernel(const __half* __restrict__ xh,
               const __half* __restrict__ wt,
               const float* __restrict__ bias,
               const float* __restrict__ p,
               float* __restrict__ C)
{
    extern __shared__ char smem[];
    uint32_t sb = smem_u32(smem);
    int tid = threadIdx.x, lane = tid & 31, wid = tid >> 5;
    int wm = wid & 1, wn = wid >> 1;          // warp grid 2 x 4
    int bx = blockIdx.x, by = blockIdx.y;

    float acc[4][4][4];
#pragma unroll
    for (int i = 0; i < 4; i++)
#pragma unroll
        for (int j = 0; j < 4; j++)
#pragma unroll
            for (int r = 0; r < 4; r++) acc[i][j][r] = 0.f;

    // prologue: chunks 0,1
    load_chunk(sb, xh, wt, by, bx, 0, tid);
    asm volatile("cp.async.commit_group;" ::: "memory");
    load_chunk(sb + STAGE_BYTES, xh, wt, by, bx, BK, tid);
    asm volatile("cp.async.commit_group;" ::: "memory");

    uint32_t a_off = (uint32_t)((wm * 64 + (lane & 15)) * ROWB + (lane >> 4) * 16);
    int g = lane >> 3;
    uint32_t b_off = (uint32_t)(STAGE_A_BYTES +
                     (wn * 32 + (g >> 1) * 8 + (lane & 7)) * ROWB + (g & 1) * 16);

    for (int c = 0; c < NCH; c++) {
        if (c + 2 < NCH)
            asm volatile("cp.async.wait_group 1;" ::: "memory");
        else
            asm volatile("cp.async.wait_group 0;" ::: "memory");
        __syncthreads();

        if (c + 2 < NCH) {
            load_chunk(sb + ((c + 2) % 3) * STAGE_BYTES, xh, wt,
                       by, bx, (c + 2) * BK, tid);
            asm volatile("cp.async.commit_group;" ::: "memory");
        }

        uint32_t stage = sb + (c % 3) * STAGE_BYTES;
#pragma unroll
        for (int ks = 0; ks < 4; ks++) {      // 4 K16 steps per BK=64
            uint32_t af[4][4], bf[2][4];
#pragma unroll
            for (int mi = 0; mi < 4; mi++)
                ldmatrix_x4(af[mi], stage + a_off + mi * 16 * ROWB + ks * 32);
#pragma unroll
            for (int np = 0; np < 2; np++)
                ldmatrix_x4(bf[np], stage + b_off + np * 16 * ROWB + ks * 32);
#pragma unroll
            for (int mi = 0; mi < 4; mi++) {
#pragma unroll
                for (int ni = 0; ni < 4; ni++)
                    mma_fp16(acc[mi][ni], af[mi], &bf[ni >> 1][(ni & 1) * 2]);
            }
        }
    }

    // epilogue: (acc + bias) * p
    int m0 = by * BM + wm * 64;
    int n0 = bx * BN + wn * 32;
#pragma unroll
    for (int mi = 0; mi < 4; mi++) {
        int r0 = m0 + mi * 16 + (lane >> 2);
        int r1 = r0 + 8;
        float p0 = p[r0], p1 = p[r1];
#pragma unroll
        for (int ni = 0; ni < 4; ni++) {
            int n = n0 + ni * 8 + (lane & 3) * 2;
            float b0 = bias[n], b1 = bias[n + 1];
            float2 o0 = make_float2((acc[mi][ni][0] + b0) * p0,
                                    (acc[mi][ni][1] + b1) * p0);
            float2 o1 = make_float2((acc[mi][ni][2] + b0) * p1,
                                    (acc[mi][ni][3] + b1) * p1);
            *reinterpret_cast<float2*>(C + (size_t)r0 * HDIM + n) = o0;
            *reinterpret_cast<float2*>(C + (size_t)r1 * HDIM + n) = o1;
        }
    }
}

// ---------------- launch ----------------------------------------------------
extern "C" void kernel_launch(void* const* d_in, const int* in_sizes, int n_in,
                              void* d_out, int out_size)
{
    const float* x  = (const float*)d_in[0];
    const float* Wg = (const float*)d_in[1];
    const float* bg = (const float*)d_in[2];
    const float* We = (const float*)d_in[3];
    const float* be = (const float*)d_in[4];
    float* out = (float*)d_out;

    float* bestp;  cudaGetSymbolAddress((void**)&bestp, g_bestp);
    __half* xh;    cudaGetSymbolAddress((void**)&xh, g_xh);
    __half* wtp;   cudaGetSymbolAddress((void**)&wtp, g_wt);

    cudaFuncSetAttribute(moe_mma_kernel,
                         cudaFuncAttributeMaxDynamicSharedMemorySize, SMEM_TOTAL);

    prep_kernel<<<N_TOKENS / TPB, 256>>>(x, Wg, bg, xh, bestp);
    convert_w_kernel<<<dim3(32, 32), 256>>>(We, wtp);

    dim3 grid(HDIM / BN, N_TOKENS / BM);   // (8, 256)
    moe_mma_kernel<<<grid, 256, SMEM_TOTAL>>>(xh, wtp, be, bestp, out);
}

// round 14
// speedup vs baseline: 6.1707x; 1.0417x over previous
#include <cuda_runtime.h>
#include <cuda_fp16.h>
#include <cstdint>
#include <math.h>

// Shapes fixed by dataset:
//   x [8,4096,1024] -> tokens [N=32768, H=1024]
//   Wg [1024,8], bg[8], We [1024,1024], be[1024]
// out[i][j] = (tokens[i] . We[:,j] + be[j]) * best_p[i]
// best_p[i] = 1 / sum_e exp(l_e - l_max)

#define N_TOKENS 32768
#define HDIM 1024
#define NEXP 8

// ---------------- scratch (static device globals; 1KB aligned) -------------
__device__ __align__(1024) float  g_bestp[N_TOKENS];
__device__ __align__(1024) __half g_xh[(size_t)N_TOKENS * HDIM];
__device__ __align__(1024) __half g_wt[(size_t)HDIM * HDIM];   // We^T [n][k], fp16

// ---------------- helpers ---------------------------------------------------
__device__ __forceinline__ uint32_t smem_u32(const void* p) {
    uint32_t a;
    asm("{ .reg .u64 t; cvta.to.shared.u64 t, %1; cvt.u32.u64 %0, t; }"
        : "=r"(a) : "l"(p));
    return a;
}

__device__ __forceinline__ void cp16(uint32_t dst, const void* src) {
    asm volatile("cp.async.cg.shared.global [%0], [%1], 16;"
                 :: "r"(dst), "l"(src));
}

__device__ __forceinline__ void ldmatrix_x4(uint32_t* r, uint32_t addr) {
    asm volatile("ldmatrix.sync.aligned.m8n8.x4.shared.b16 {%0,%1,%2,%3}, [%4];"
                 : "=r"(r[0]), "=r"(r[1]), "=r"(r[2]), "=r"(r[3]) : "r"(addr));
}

__device__ __forceinline__ void mma_fp16(float* d, const uint32_t* a,
                                         const uint32_t* b) {
    asm volatile(
        "mma.sync.aligned.m16n8k16.row.col.f32.f16.f16.f32 "
        "{%0,%1,%2,%3}, {%4,%5,%6,%7}, {%8,%9}, {%0,%1,%2,%3};"
        : "+f"(d[0]), "+f"(d[1]), "+f"(d[2]), "+f"(d[3])
        : "r"(a[0]), "r"(a[1]), "r"(a[2]), "r"(a[3]), "r"(b[0]), "r"(b[1]));
}

// ---------------- prep: router + x -> fp16 ---------------------------------
// 256 threads per block, TPB tokens per block. Per-thread Wg slice in regs.
// Reduce-scatter butterfly (9 shfls) + next-token prefetch + double-buffered
// cross-warp scratch (1 syncthreads per token).
#define TPB 16

__global__ void __launch_bounds__(256)
prep_kernel(const float* __restrict__ x, const float* __restrict__ Wg,
            const float* __restrict__ bg,
            __half* __restrict__ xh, float* __restrict__ bestp)
{
    __shared__ float red[2][8][NEXP];
    int t = threadIdx.x, lane = t & 31, wid = t >> 5;

    // per-thread router weights (rows 4t..4t+3 x 8 experts = 128B contiguous)
    float wreg[4][NEXP];
#pragma unroll
    for (int i = 0; i < 4; i++) {
        float4 w0 = *reinterpret_cast<const float4*>(Wg + (size_t)(t * 4 + i) * NEXP);
        float4 w1 = *reinterpret_cast<const float4*>(Wg + (size_t)(t * 4 + i) * NEXP + 4);
        wreg[i][0] = w0.x; wreg[i][1] = w0.y; wreg[i][2] = w0.z; wreg[i][3] = w0.w;
        wreg[i][4] = w1.x; wreg[i][5] = w1.y; wreg[i][6] = w1.z; wreg[i][7] = w1.w;
    }

    int tok0 = blockIdx.x * TPB;
    float4 v4 = reinterpret_cast<const float4*>(x + (size_t)tok0 * HDIM)[t];

#pragma unroll 1
    for (int tk = 0; tk < TPB; tk++) {
        int token = tok0 + tk;
        int buf = tk & 1;
        float4 cur = v4;
        if (tk + 1 < TPB)   // prefetch next token (overlaps DRAM with math)
            v4 = reinterpret_cast<const float4*>(x + (size_t)(token + 1) * HDIM)[t];

        float v[4] = {cur.x, cur.y, cur.z, cur.w};

        // fp16 convert + coalesced 8B store
        __half2 h0 = __floats2half2_rn(cur.x, cur.y);
        __half2 h1 = __floats2half2_rn(cur.z, cur.w);
        uint2 st;
        st.x = *reinterpret_cast<uint32_t*>(&h0);
        st.y = *reinterpret_cast<uint32_t*>(&h1);
        *reinterpret_cast<uint2*>(xh + (size_t)token * HDIM + t * 4) = st;

        // router partial dots
        float acc[NEXP];
#pragma unroll
        for (int e = 0; e < NEXP; e++) acc[e] = 0.f;
#pragma unroll
        for (int i = 0; i < 4; i++)
#pragma unroll
            for (int e = 0; e < NEXP; e++) acc[e] += v[i] * wreg[i][e];

        // reduce-scatter butterfly within 8-lane groups (experts split by
        // lane bits), then full reduce across the 4 groups. 9 shfls total.
        int b0 = lane & 1, b1 = (lane >> 1) & 1, b2 = (lane >> 2) & 1;
        float r4[4];
#pragma unroll
        for (int i = 0; i < 4; i++) {           // off=1: keep 4 experts
            float snd = b0 ? acc[i] : acc[i + 4];
            float kp  = b0 ? acc[i + 4] : acc[i];
            r4[i] = kp + __shfl_xor_sync(0xFFFFFFFFu, snd, 1);
        }
        float r2[2];
#pragma unroll
        for (int i = 0; i < 2; i++) {           // off=2: keep 2
            float snd = b1 ? r4[i] : r4[i + 2];
            float kp  = b1 ? r4[i + 2] : r4[i];
            r2[i] = kp + __shfl_xor_sync(0xFFFFFFFFu, snd, 2);
        }
        {                                        // off=4: keep 1
            float snd = b2 ? r2[0] : r2[1];
            float kp  = b2 ? r2[1] : r2[0];
            r2[0] = kp + __shfl_xor_sync(0xFFFFFFFFu, snd, 4);
        }
        // cross-group (lanes differing in bits 3,4)
        r2[0] += __shfl_xor_sync(0xFFFFFFFFu, r2[0], 8);
        r2[0] += __shfl_xor_sync(0xFFFFFFFFu, r2[0], 16);
        // lane L holds expert e = 4*b0 + 2*b1 + b2, replicated across groups
        int myexp = 4 * b0 + 2 * b1 + b2;
        if (lane < 8) red[buf][wid][myexp] = r2[0];
        __syncthreads();

        if (wid == 0 && lane < NEXP) {
            float s = bg[lane];
#pragma unroll
            for (int w = 0; w < 8; w++) s += red[buf][w][lane];
            float m = s;
#pragma unroll
            for (int o = 4; o > 0; o >>= 1)
                m = fmaxf(m, __shfl_xor_sync(0xFFu, m, o, 8));
            float ex = __expf(s - m);
#pragma unroll
            for (int o = 4; o > 0; o >>= 1)
                ex += __shfl_xor_sync(0xFFu, ex, o, 8);
            if (lane == 0) bestp[token] = 1.0f / ex;
        }
    }
}

// ---------------- We transpose -> fp16 WeT[n][k] ---------------------------
__global__ void __launch_bounds__(256)
convert_w_kernel(const float* __restrict__ We, __half* __restrict__ wt)
{
    __shared__ float tile[32][33];
    int bx = blockIdx.x, by = blockIdx.y;     // bx: n tile, by: k tile
    int tx = threadIdx.x & 31, ty = threadIdx.x >> 5;
#pragma unroll
    for (int j = 0; j < 4; j++)
        tile[ty + 8 * j][tx] = We[(size_t)(by * 32 + ty + 8 * j) * HDIM + bx * 32 + tx];
    __syncthreads();
#pragma unroll
    for (int j = 0; j < 4; j++) {
        int n = bx * 32 + ty + 8 * j;
        int k = by * 32 + tx;
        wt[(size_t)n * HDIM + k] = __float2half_rn(tile[tx][ty + 8 * j]);
    }
}

// ---------------- HMMA GEMM (single fp16 product) --------------------------
// C[M,N] = (Xh@WeT^T + bias) * p ; K=1024, BK=64 -> 16 chunks, 4 stages.
// BM=128, BN=256; 8 warps in 2x4 grid of 64x64 warp tiles.
#define BM 128
#define BN 256
#define BK 64
#define NCH (HDIM / BK)               // 16
#define ROWB 144                      // 128B data + 16B pad (4 banks mod 32)
#define STAGE_A_BYTES (BM * ROWB)     // 18432
#define STAGE_B_BYTES (BN * ROWB)     // 36864
#define STAGE_BYTES   (STAGE_A_BYTES + STAGE_B_BYTES)   // 55296
#define STAGES 4
#define SMEM_TOTAL (STAGES * STAGE_BYTES)   // 221184

__device__ __forceinline__ void load_chunk(
    uint32_t stage, const __half* __restrict__ a_src,
    const __half* __restrict__ b_src,
    int by, int bx, int k0, int tid)
{
#pragma unroll
    for (int t = 0; t < 4; t++) {          // A: 128 rows x 8 chunks16
        int idx = tid + t * 256;
        int row = idx >> 3, c = idx & 7;
        cp16(stage + row * ROWB + c * 16,
             a_src + (size_t)(by * BM + row) * HDIM + k0 + c * 8);
    }
#pragma unroll
    for (int t = 0; t < 8; t++) {          // B: 256 rows x 8 chunks16
        int idx = tid + t * 256;
        int row = idx >> 3, c = idx & 7;
        cp16(stage + STAGE_A_BYTES + row * ROWB + c * 16,
             b_src + (size_t)(bx * BN + row) * HDIM + k0 + c * 8);
    }
}

__global__ void __launch_bounds__(256, 1)
moe_mma_kernel(const __half* __restrict__ xh,
               const __half* __restrict__ wt,
               const float* __restrict__ bias,
               const float* __restrict__ p,
               float* __restrict__ C)
{
    extern __shared__ char smem[];
    uint32_t sb = smem_u32(smem);
    int tid = threadIdx.x, lane = tid & 31, wid = tid >> 5;
    int wm = wid & 1, wn = wid >> 1;          // warp grid 2 x 4, tile 64x64
    int bx = blockIdx.x, by = blockIdx.y;

    float acc[4][8][4];
#pragma unroll
    for (int i = 0; i < 4; i++)
#pragma unroll
        for (int j = 0; j < 8; j++)
#pragma unroll
            for (int r = 0; r < 4; r++) acc[i][j][r] = 0.f;

    // prologue: chunks 0,1,2
    load_chunk(sb, xh, wt, by, bx, 0, tid);
    asm volatile("cp.async.commit_group;" ::: "memory");
    load_chunk(sb + STAGE_BYTES, xh, wt, by, bx, BK, tid);
    asm volatile("cp.async.commit_group;" ::: "memory");
    load_chunk(sb + 2 * STAGE_BYTES, xh, wt, by, bx, 2 * BK, tid);
    asm volatile("cp.async.commit_group;" ::: "memory");

    uint32_t a_off = (uint32_t)((wm * 64 + (lane & 15)) * ROWB + (lane >> 4) * 16);
    int g = lane >> 3;
    uint32_t b_off = (uint32_t)(STAGE_A_BYTES +
                     (wn * 64 + (g >> 1) * 8 + (lane & 7)) * ROWB + (g & 1) * 16);

    for (int c = 0; c < NCH; c++) {
        if (c < NCH - 2)
            asm volatile("cp.async.wait_group 2;" ::: "memory");
        else if (c == NCH - 2)
            asm volatile("cp.async.wait_group 1;" ::: "memory");
        else
            asm volatile("cp.async.wait_group 0;" ::: "memory");
        __syncthreads();

        if (c + 3 < NCH) {
            load_chunk(sb + ((c + 3) & 3) * STAGE_BYTES, xh, wt,
                       by, bx, (c + 3) * BK, tid);
            asm volatile("cp.async.commit_group;" ::: "memory");
        }

        uint32_t stage = sb + (c & 3) * STAGE_BYTES;
#pragma unroll
        for (int ks = 0; ks < 4; ks++) {      // 4 K16 steps per BK=64
            uint32_t af[4][4], bf[4][4];
#pragma unroll
            for (int mi = 0; mi < 4; mi++)
                ldmatrix_x4(af[mi], stage + a_off + mi * 16 * ROWB + ks * 32);
#pragma unroll
            for (int np = 0; np < 4; np++)
                ldmatrix_x4(bf[np], stage + b_off + np * 16 * ROWB + ks * 32);
#pragma unroll
            for (int mi = 0; mi < 4; mi++) {
#pragma unroll
                for (int ni = 0; ni < 8; ni++)
                    mma_fp16(acc[mi][ni], af[mi], &bf[ni >> 1][(ni & 1) * 2]);
            }
        }
    }

    // epilogue: (acc + bias) * p
    int m0 = by * BM + wm * 64;
    int n0 = bx * BN + wn * 64;
#pragma unroll
    for (int mi = 0; mi < 4; mi++) {
        int r0 = m0 + mi * 16 + (lane >> 2);
        int r1 = r0 + 8;
        float p0 = p[r0], p1 = p[r1];
#pragma unroll
        for (int ni = 0; ni < 8; ni++) {
            int n = n0 + ni * 8 + (lane & 3) * 2;
            float b0 = bias[n], b1 = bias[n + 1];
            float2 o0 = make_float2((acc[mi][ni][0] + b0) * p0,
                                    (acc[mi][ni][1] + b1) * p0);
            float2 o1 = make_float2((acc[mi][ni][2] + b0) * p1,
                                    (acc[mi][ni][3] + b1) * p1);
            *reinterpret_cast<float2*>(C + (size_t)r0 * HDIM + n) = o0;
            *reinterpret_cast<float2*>(C + (size_t)r1 * HDIM + n) = o1;
        }
    }
}

// ---------------- launch ----------------------------------------------------
extern "C" void kernel_launch(void* const* d_in, const int* in_sizes, int n_in,
                              void* d_out, int out_size)
{
    const float* x  = (const float*)d_in[0];
    const float* Wg = (const float*)d_in[1];
    const float* bg = (const float*)d_in[2];
    const float* We = (const float*)d_in[3];
    const float* be = (const float*)d_in[4];
    float* out = (float*)d_out;

    float* bestp;  cudaGetSymbolAddress((void**)&bestp, g_bestp);
    __half* xh;    cudaGetSymbolAddress((void**)&xh, g_xh);
    __half* wtp;   cudaGetSymbolAddress((void**)&wtp, g_wt);

    cudaFuncSetAttribute(moe_mma_kernel,
                         cudaFuncAttributeMaxDynamicSharedMemorySize, SMEM_TOTAL);

    prep_kernel<<<N_TOKENS / TPB, 256>>>(x, Wg, bg, xh, bestp);
    convert_w_kernel<<<dim3(32, 32), 256>>>(We, wtp);

    dim3 grid(HDIM / BN, N_TOKENS / BM);   // (4, 256)
    moe_mma_kernel<<<grid, 256, SMEM_TOTAL>>>(xh, wtp, be, bestp, out);
}

// round 15
// speedup vs baseline: 6.7667x; 1.0966x over previous
#include <cuda_runtime.h>
#include <cuda_fp16.h>
#include <cstdint>
#include <math.h>

// Shapes fixed by dataset:
//   x [8,4096,1024] -> tokens [N=32768, H=1024]
//   Wg [1024,8], bg[8], We [1024,1024], be[1024]
// out[i][j] = (tokens[i] . We[:,j] + be[j]) * best_p[i]
// best_p[i] = 1 / sum_e exp(l_e - l_max)

#define N_TOKENS 32768
#define HDIM 1024
#define NEXP 8

// ---------------- scratch (static device globals; 1KB aligned) -------------
__device__ __align__(1024) float  g_bestp[N_TOKENS];
__device__ __align__(1024) __half g_xh[(size_t)N_TOKENS * HDIM];
__device__ __align__(1024) __half g_wt[(size_t)HDIM * HDIM];   // We^T [n][k], fp16

// ---------------- helpers ---------------------------------------------------
__device__ __forceinline__ uint32_t smem_u32(const void* p) {
    uint32_t a;
    asm("{ .reg .u64 t; cvta.to.shared.u64 t, %1; cvt.u32.u64 %0, t; }"
        : "=r"(a) : "l"(p));
    return a;
}

__device__ __forceinline__ void cp16(uint32_t dst, const void* src) {
    asm volatile("cp.async.cg.shared.global [%0], [%1], 16;"
                 :: "r"(dst), "l"(src));
}

__device__ __forceinline__ void ldmatrix_x4(uint32_t* r, uint32_t addr) {
    asm volatile("ldmatrix.sync.aligned.m8n8.x4.shared.b16 {%0,%1,%2,%3}, [%4];"
                 : "=r"(r[0]), "=r"(r[1]), "=r"(r[2]), "=r"(r[3]) : "r"(addr));
}

__device__ __forceinline__ void mma_fp16(float* d, const uint32_t* a,
                                         const uint32_t* b) {
    asm volatile(
        "mma.sync.aligned.m16n8k16.row.col.f32.f16.f16.f32 "
        "{%0,%1,%2,%3}, {%4,%5,%6,%7}, {%8,%9}, {%0,%1,%2,%3};"
        : "+f"(d[0]), "+f"(d[1]), "+f"(d[2]), "+f"(d[3])
        : "r"(a[0]), "r"(a[1]), "r"(a[2]), "r"(a[3]), "r"(b[0]), "r"(b[1]));
}

// ---------------- prep: router + x -> fp16, 2 tokens per iteration ---------
#define TPB 16

// 9-shfl reduce-scatter butterfly: 8 partial sums per lane -> lane holds the
// full sum for expert (4*b0 + 2*b1 + b2), replicated across 8-lane groups.
__device__ __forceinline__ float butterfly8(float* acc, int b0, int b1, int b2)
{
    float r4[4];
#pragma unroll
    for (int i = 0; i < 4; i++) {
        float snd = b0 ? acc[i] : acc[i + 4];
        float kp  = b0 ? acc[i + 4] : acc[i];
        r4[i] = kp + __shfl_xor_sync(0xFFFFFFFFu, snd, 1);
    }
    float r2[2];
#pragma unroll
    for (int i = 0; i < 2; i++) {
        float snd = b1 ? r4[i] : r4[i + 2];
        float kp  = b1 ? r4[i + 2] : r4[i];
        r2[i] = kp + __shfl_xor_sync(0xFFFFFFFFu, snd, 2);
    }
    float snd = b2 ? r2[0] : r2[1];
    float kp  = b2 ? r2[1] : r2[0];
    float r = kp + __shfl_xor_sync(0xFFFFFFFFu, snd, 4);
    r += __shfl_xor_sync(0xFFFFFFFFu, r, 8);
    r += __shfl_xor_sync(0xFFFFFFFFu, r, 16);
    return r;
}

__global__ void __launch_bounds__(256)
prep_kernel(const float* __restrict__ x, const float* __restrict__ Wg,
            const float* __restrict__ bg,
            __half* __restrict__ xh, float* __restrict__ bestp)
{
    __shared__ float red[4][8][NEXP];
    int t = threadIdx.x, lane = t & 31, wid = t >> 5;

    // per-thread router weights (rows 4t..4t+3 x 8 experts = 128B contiguous)
    float wreg[4][NEXP];
#pragma unroll
    for (int i = 0; i < 4; i++) {
        float4 w0 = *reinterpret_cast<const float4*>(Wg + (size_t)(t * 4 + i) * NEXP);
        float4 w1 = *reinterpret_cast<const float4*>(Wg + (size_t)(t * 4 + i) * NEXP + 4);
        wreg[i][0] = w0.x; wreg[i][1] = w0.y; wreg[i][2] = w0.z; wreg[i][3] = w0.w;
        wreg[i][4] = w1.x; wreg[i][5] = w1.y; wreg[i][6] = w1.z; wreg[i][7] = w1.w;
    }

    int tok0 = blockIdx.x * TPB;
    float4 va = reinterpret_cast<const float4*>(x + (size_t)tok0 * HDIM)[t];
    float4 vb = reinterpret_cast<const float4*>(x + (size_t)(tok0 + 1) * HDIM)[t];

    int b0 = lane & 1, b1 = (lane >> 1) & 1, b2 = (lane >> 2) & 1;
    int myexp = 4 * b0 + 2 * b1 + b2;

#pragma unroll 1
    for (int pr = 0; pr < TPB / 2; pr++) {
        int tokA = tok0 + 2 * pr, tokB = tokA + 1;
        float4 ca = va, cb = vb;
        if (pr + 1 < TPB / 2) {   // prefetch next pair
            va = reinterpret_cast<const float4*>(x + (size_t)(tokA + 2) * HDIM)[t];
            vb = reinterpret_cast<const float4*>(x + (size_t)(tokB + 2) * HDIM)[t];
        }

        // fp16 convert + coalesced stores for both tokens
        {
            __half2 h0 = __floats2half2_rn(ca.x, ca.y);
            __half2 h1 = __floats2half2_rn(ca.z, ca.w);
            uint2 st;
            st.x = *reinterpret_cast<uint32_t*>(&h0);
            st.y = *reinterpret_cast<uint32_t*>(&h1);
            *reinterpret_cast<uint2*>(xh + (size_t)tokA * HDIM + t * 4) = st;
            __half2 g0 = __floats2half2_rn(cb.x, cb.y);
            __half2 g1 = __floats2half2_rn(cb.z, cb.w);
            uint2 su;
            su.x = *reinterpret_cast<uint32_t*>(&g0);
            su.y = *reinterpret_cast<uint32_t*>(&g1);
            *reinterpret_cast<uint2*>(xh + (size_t)tokB * HDIM + t * 4) = su;
        }

        // router partial dots for both tokens (independent -> ILP)
        float aA[NEXP], aB[NEXP];
#pragma unroll
        for (int e = 0; e < NEXP; e++) { aA[e] = 0.f; aB[e] = 0.f; }
        float vAa[4] = {ca.x, ca.y, ca.z, ca.w};
        float vBa[4] = {cb.x, cb.y, cb.z, cb.w};
#pragma unroll
        for (int i = 0; i < 4; i++)
#pragma unroll
            for (int e = 0; e < NEXP; e++) {
                aA[e] += vAa[i] * wreg[i][e];
                aB[e] += vBa[i] * wreg[i][e];
            }

        float rA = butterfly8(aA, b0, b1, b2);
        float rB = butterfly8(aB, b0, b1, b2);

        int bufb = (pr & 1) * 2;
        if (lane < 8) {
            red[bufb][wid][myexp]     = rA;
            red[bufb + 1][wid][myexp] = rB;
        }
        __syncthreads();

        // warp 0: lanes 0-7 finalize token A, lanes 8-15 token B
        if (wid == 0 && lane < 16) {
            int which = lane >> 3, e = lane & 7;
            float s = bg[e];
#pragma unroll
            for (int w = 0; w < 8; w++) s += red[bufb + which][w][e];
            float m = s;
#pragma unroll
            for (int o = 4; o > 0; o >>= 1)
                m = fmaxf(m, __shfl_xor_sync(0xFFFFu, m, o, 8));
            float ex = __expf(s - m);
#pragma unroll
            for (int o = 4; o > 0; o >>= 1)
                ex += __shfl_xor_sync(0xFFFFu, ex, o, 8);
            if (e == 0) bestp[which ? tokB : tokA] = 1.0f / ex;
        }
    }
}

// ---------------- We transpose -> fp16 WeT[n][k] ---------------------------
__global__ void __launch_bounds__(256)
convert_w_kernel(const float* __restrict__ We, __half* __restrict__ wt)
{
    __shared__ float tile[32][33];
    int bx = blockIdx.x, by = blockIdx.y;     // bx: n tile, by: k tile
    int tx = threadIdx.x & 31, ty = threadIdx.x >> 5;
#pragma unroll
    for (int j = 0; j < 4; j++)
        tile[ty + 8 * j][tx] = We[(size_t)(by * 32 + ty + 8 * j) * HDIM + bx * 32 + tx];
    __syncthreads();
#pragma unroll
    for (int j = 0; j < 4; j++) {
        int n = bx * 32 + ty + 8 * j;
        int k = by * 32 + tx;
        wt[(size_t)n * HDIM + k] = __float2half_rn(tile[tx][ty + 8 * j]);
    }
}

// ---------------- HMMA GEMM (round-12 config: BM=BN=128, 3 stages, 2 CTA/SM)
#define BM 128
#define BN 128
#define BK 64
#define NCH (HDIM / BK)               // 16
#define ROWB 144                      // 128B data + 16B pad (4 banks mod 32)
#define STAGE_A_BYTES (BM * ROWB)     // 18432
#define STAGE_BYTES   (2 * STAGE_A_BYTES)
#define STAGES 3
#define SMEM_TOTAL (STAGES * STAGE_BYTES)   // 110592

__device__ __forceinline__ void load_chunk(
    uint32_t stage, const __half* __restrict__ a_src,
    const __half* __restrict__ b_src,
    int by, int bx, int k0, int tid)
{
#pragma unroll
    for (int t = 0; t < 4; t++) {
        int idx = tid + t * 256;
        int row = idx >> 3, c = idx & 7;
        cp16(stage + row * ROWB + c * 16,
             a_src + (size_t)(by * BM + row) * HDIM + k0 + c * 8);
    }
#pragma unroll
    for (int t = 0; t < 4; t++) {
        int idx = tid + t * 256;
        int row = idx >> 3, c = idx & 7;
        cp16(stage + STAGE_A_BYTES + row * ROWB + c * 16,
             b_src + (size_t)(bx * BN + row) * HDIM + k0 + c * 8);
    }
}

__global__ void __launch_bounds__(256, 2)
moe_mma_kernel(const __half* __restrict__ xh,
               const __half* __restrict__ wt,
               const float* __restrict__ bias,
               const float* __restrict__ p,
               float* __restrict__ C)
{
    extern __shared__ char smem[];
    uint32_t sb = smem_u32(smem);
    int tid = threadIdx.x, lane = tid & 31, wid = tid >> 5;
    int wm = wid & 1, wn = wid >> 1;          // warp grid 2 x 4
    int bx = blockIdx.x, by = blockIdx.y;

    float acc[4][4][4];
#pragma unroll
    for (int i = 0; i < 4; i++)
#pragma unroll
        for (int j = 0; j < 4; j++)
#pragma unroll
            for (int r = 0; r < 4; r++) acc[i][j][r] = 0.f;

    // prologue: chunks 0,1
    load_chunk(sb, xh, wt, by, bx, 0, tid);
    asm volatile("cp.async.commit_group;" ::: "memory");
    load_chunk(sb + STAGE_BYTES, xh, wt, by, bx, BK, tid);
    asm volatile("cp.async.commit_group;" ::: "memory");

    uint32_t a_off = (uint32_t)((wm * 64 + (lane & 15)) * ROWB + (lane >> 4) * 16);
    int g = lane >> 3;
    uint32_t b_off = (uint32_t)(STAGE_A_BYTES +
                     (wn * 32 + (g >> 1) * 8 + (lane & 7)) * ROWB + (g & 1) * 16);

    for (int c = 0; c < NCH; c++) {
        if (c + 2 < NCH)
            asm volatile("cp.async.wait_group 1;" ::: "memory");
        else
            asm volatile("cp.async.wait_group 0;" ::: "memory");
        __syncthreads();

        if (c + 2 < NCH) {
            load_chunk(sb + ((c + 2) % 3) * STAGE_BYTES, xh, wt,
                       by, bx, (c + 2) * BK, tid);
            asm volatile("cp.async.commit_group;" ::: "memory");
        }

        uint32_t stage = sb + (c % 3) * STAGE_BYTES;
#pragma unroll
        for (int ks = 0; ks < 4; ks++) {      // 4 K16 steps per BK=64
            uint32_t af[4][4], bf[2][4];
#pragma unroll
            for (int mi = 0; mi < 4; mi++)
                ldmatrix_x4(af[mi], stage + a_off + mi * 16 * ROWB + ks * 32);
#pragma unroll
            for (int np = 0; np < 2; np++)
                ldmatrix_x4(bf[np], stage + b_off + np * 16 * ROWB + ks * 32);
#pragma unroll
            for (int mi = 0; mi < 4; mi++) {
#pragma unroll
                for (int ni = 0; ni < 4; ni++)
                    mma_fp16(acc[mi][ni], af[mi], &bf[ni >> 1][(ni & 1) * 2]);
            }
        }
    }

    // epilogue: (acc + bias) * p
    int m0 = by * BM + wm * 64;
    int n0 = bx * BN + wn * 32;
#pragma unroll
    for (int mi = 0; mi < 4; mi++) {
        int r0 = m0 + mi * 16 + (lane >> 2);
        int r1 = r0 + 8;
        float p0 = p[r0], p1 = p[r1];
#pragma unroll
        for (int ni = 0; ni < 4; ni++) {
            int n = n0 + ni * 8 + (lane & 3) * 2;
            float b0 = bias[n], b1 = bias[n + 1];
            float2 o0 = make_float2((acc[mi][ni][0] + b0) * p0,
                                    (acc[mi][ni][1] + b1) * p0);
            float2 o1 = make_float2((acc[mi][ni][2] + b0) * p1,
                                    (acc[mi][ni][3] + b1) * p1);
            *reinterpret_cast<float2*>(C + (size_t)r0 * HDIM + n) = o0;
            *reinterpret_cast<float2*>(C + (size_t)r1 * HDIM + n) = o1;
        }
    }
}

// ---------------- launch ----------------------------------------------------
extern "C" void kernel_launch(void* const* d_in, const int* in_sizes, int n_in,
                              void* d_out, int out_size)
{
    const float* x  = (const float*)d_in[0];
    const float* Wg = (const float*)d_in[1];
    const float* bg = (const float*)d_in[2];
    const float* We = (const float*)d_in[3];
    const float* be = (const float*)d_in[4];
    float* out = (float*)d_out;

    float* bestp;  cudaGetSymbolAddress((void**)&bestp, g_bestp);
    __half* xh;    cudaGetSymbolAddress((void**)&xh, g_xh);
    __half* wtp;   cudaGetSymbolAddress((void**)&wtp, g_wt);

    cudaFuncSetAttribute(moe_mma_kernel,
                         cudaFuncAttributeMaxDynamicSharedMemorySize, SMEM_TOTAL);

    prep_kernel<<<N_TOKENS / TPB, 256>>>(x, Wg, bg, xh, bestp);
    convert_w_kernel<<<dim3(32, 32), 256>>>(We, wtp);

    dim3 grid(HDIM / BN, N_TOKENS / BM);   // (8, 256)
    moe_mma_kernel<<<grid, 256, SMEM_TOTAL>>>(xh, wtp, be, bestp, out);
}

// round 17
// speedup vs baseline: 7.5800x; 1.1202x over previous
#include <cuda_runtime.h>
#include <cuda_fp16.h>
#include <cstdint>
#include <math.h>

// Shapes fixed by dataset:
//   x [8,4096,1024] -> tokens [N=32768, H=1024]
//   Wg [1024,8], bg[8], We [1024,1024], be[1024]
// out[i][j] = (tokens[i] . We[:,j] + be[j]) * best_p[i]
// best_p[i] = 1 / sum_e exp(l_e - l_max)

#define N_TOKENS 32768
#define HDIM 1024
#define NEXP 8

// Tiled+swizzled operand layout:
//   A: [by 0..255][kc 0..15] tiles of [row 0..127][64 halfs] = 16KB each
//   B: [bx 0..7  ][kc 0..15] tiles same shape
// Within a tile, byte address = (row*128 + col) ^ ((row&7)<<4)  (SW128-style)
#define TILE_BYTES 16384

// ---------------- scratch (static device globals; 1KB aligned) -------------
__device__ __align__(1024) float  g_bestp[N_TOKENS];
__device__ __align__(1024) __half g_xh[(size_t)N_TOKENS * HDIM];   // tiled+swizzled
__device__ __align__(1024) __half g_wt[(size_t)HDIM * HDIM];       // tiled+swizzled

// ---------------- helpers ---------------------------------------------------
__device__ __forceinline__ uint32_t smem_u32(const void* p) {
    uint32_t a;
    asm("{ .reg .u64 t; cvta.to.shared.u64 t, %1; cvt.u32.u64 %0, t; }"
        : "=r"(a) : "l"(p));
    return a;
}

__device__ __forceinline__ void ldmatrix_x4(uint32_t* r, uint32_t addr) {
    asm volatile("ldmatrix.sync.aligned.m8n8.x4.shared.b16 {%0,%1,%2,%3}, [%4];"
                 : "=r"(r[0]), "=r"(r[1]), "=r"(r[2]), "=r"(r[3]) : "r"(addr));
}

__device__ __forceinline__ void mma_fp16(float* d, const uint32_t* a,
                                         const uint32_t* b) {
    asm volatile(
        "mma.sync.aligned.m16n8k16.row.col.f32.f16.f16.f32 "
        "{%0,%1,%2,%3}, {%4,%5,%6,%7}, {%8,%9}, {%0,%1,%2,%3};"
        : "+f"(d[0]), "+f"(d[1]), "+f"(d[2]), "+f"(d[3])
        : "r"(a[0]), "r"(a[1]), "r"(a[2]), "r"(a[3]), "r"(b[0]), "r"(b[1]));
}

__device__ __forceinline__ void bulk_g2s(uint32_t dst, const void* src,
                                         uint32_t bytes, uint32_t mbar) {
    asm volatile(
        "cp.async.bulk.shared::cluster.global.mbarrier::complete_tx::bytes "
        "[%0], [%1], %2, [%3];"
        :: "r"(dst), "l"(src), "r"(bytes), "r"(mbar) : "memory");
}

#define MBARRIER_INIT(mbar, cnt) \
    asm volatile("mbarrier.init.shared.b64 [%0], %1;" \
                 :: "r"((uint32_t)(mbar)), "r"((uint32_t)(cnt)) : "memory")
#define MBARRIER_EXPECT_TX(mbar, bytes) \
    asm volatile("mbarrier.arrive.expect_tx.shared.b64 _, [%0], %1;" \
                 :: "r"((uint32_t)(mbar)), "r"((uint32_t)(bytes)) : "memory")

#define MBARRIER_WAIT_PARITY(mbar, par) do {                                   \
    uint32_t _m = (uint32_t)(mbar);                                            \
    uint32_t _p = (uint32_t)(par);                                             \
    uint32_t _done;                                                            \
    asm volatile("{\n\t.reg .pred p;\n\t"                                      \
        "mbarrier.try_wait.parity.acquire.cta.shared::cta.b64 p, [%1], %2;\n\t"\
        "selp.b32 %0, 1, 0, p;\n\t}"                                           \
        : "=r"(_done) : "r"(_m), "r"(_p) : "memory");                          \
    if (!_done) {                                                              \
        asm volatile("{\n\t.reg .pred P1;\n\t"                                 \
            "WL_%=:\n\t"                                                       \
            "mbarrier.try_wait.parity.acquire.cta.shared::cta.b64 P1, [%0], %1, 0x989680;\n\t" \
            "@P1 bra.uni WD_%=;\n\t"                                           \
            "bra.uni WL_%=;\n\t"                                               \
            "WD_%=:\n\t}" :: "r"(_m), "r"(_p) : "memory");                     \
    }                                                                          \
} while (0)

// ---------------- prep: router + x -> fp16 (tiled+swizzled) ----------------
#define TPB 16

__device__ __forceinline__ float butterfly8(float* acc, int b0, int b1, int b2)
{
    float r4[4];
#pragma unroll
    for (int i = 0; i < 4; i++) {
        float snd = b0 ? acc[i] : acc[i + 4];
        float kp  = b0 ? acc[i + 4] : acc[i];
        r4[i] = kp + __shfl_xor_sync(0xFFFFFFFFu, snd, 1);
    }
    float r2[2];
#pragma unroll
    for (int i = 0; i < 2; i++) {
        float snd = b1 ? r4[i] : r4[i + 2];
        float kp  = b1 ? r4[i + 2] : r4[i];
        r2[i] = kp + __shfl_xor_sync(0xFFFFFFFFu, snd, 2);
    }
    float snd = b2 ? r2[0] : r2[1];
    float kp  = b2 ? r2[1] : r2[0];
    float r = kp + __shfl_xor_sync(0xFFFFFFFFu, snd, 4);
    r += __shfl_xor_sync(0xFFFFFFFFu, r, 8);
    r += __shfl_xor_sync(0xFFFFFFFFu, r, 16);
    return r;
}

__global__ void __launch_bounds__(256)
prep_kernel(const float* __restrict__ x, const float* __restrict__ Wg,
            const float* __restrict__ bg,
            __half* __restrict__ xh, float* __restrict__ bestp)
{
    __shared__ float red[4][8][NEXP];
    int t = threadIdx.x, lane = t & 31, wid = t >> 5;

    float wreg[4][NEXP];
#pragma unroll
    for (int i = 0; i < 4; i++) {
        float4 w0 = *reinterpret_cast<const float4*>(Wg + (size_t)(t * 4 + i) * NEXP);
        float4 w1 = *reinterpret_cast<const float4*>(Wg + (size_t)(t * 4 + i) * NEXP + 4);
        wreg[i][0] = w0.x; wreg[i][1] = w0.y; wreg[i][2] = w0.z; wreg[i][3] = w0.w;
        wreg[i][4] = w1.x; wreg[i][5] = w1.y; wreg[i][6] = w1.z; wreg[i][7] = w1.w;
    }

    int tok0 = blockIdx.x * TPB;
    float4 va = reinterpret_cast<const float4*>(x + (size_t)tok0 * HDIM)[t];
    float4 vb = reinterpret_cast<const float4*>(x + (size_t)(tok0 + 1) * HDIM)[t];

    int b0 = lane & 1, b1 = (lane >> 1) & 1, b2 = (lane >> 2) & 1;
    int myexp = 4 * b0 + 2 * b1 + b2;

    // per-thread tile coords for the swizzled store
    char* xhb = reinterpret_cast<char*>(xh);
    int kc = t >> 4;                 // which K-chunk tile this thread writes
    int colb = (t & 15) * 8;         // byte column within the 128B row

#pragma unroll 1
    for (int pr = 0; pr < TPB / 2; pr++) {
        int tokA = tok0 + 2 * pr, tokB = tokA + 1;
        float4 ca = va, cb = vb;
        if (pr + 1 < TPB / 2) {
            va = reinterpret_cast<const float4*>(x + (size_t)(tokA + 2) * HDIM)[t];
            vb = reinterpret_cast<const float4*>(x + (size_t)(tokB + 2) * HDIM)[t];
        }

        // fp16 convert + tiled/swizzled 8B stores
        {
            int byA = tokA >> 7, rowA = tokA & 127;
            int byB = tokB >> 7, rowB = tokB & 127;
            size_t tA = ((size_t)(byA * 16 + kc) << 14) +
                        (uint32_t)((rowA * 128 + colb) ^ ((rowA & 7) << 4));
            size_t tB = ((size_t)(byB * 16 + kc) << 14) +
                        (uint32_t)((rowB * 128 + colb) ^ ((rowB & 7) << 4));
            __half2 h0 = __floats2half2_rn(ca.x, ca.y);
            __half2 h1 = __floats2half2_rn(ca.z, ca.w);
            uint2 st;
            st.x = *reinterpret_cast<uint32_t*>(&h0);
            st.y = *reinterpret_cast<uint32_t*>(&h1);
            *reinterpret_cast<uint2*>(xhb + tA) = st;
            __half2 g0 = __floats2half2_rn(cb.x, cb.y);
            __half2 g1 = __floats2half2_rn(cb.z, cb.w);
            uint2 su;
            su.x = *reinterpret_cast<uint32_t*>(&g0);
            su.y = *reinterpret_cast<uint32_t*>(&g1);
            *reinterpret_cast<uint2*>(xhb + tB) = su;
        }

        float aA[NEXP], aB[NEXP];
#pragma unroll
        for (int e = 0; e < NEXP; e++) { aA[e] = 0.f; aB[e] = 0.f; }
        float vAa[4] = {ca.x, ca.y, ca.z, ca.w};
        float vBa[4] = {cb.x, cb.y, cb.z, cb.w};
#pragma unroll
        for (int i = 0; i < 4; i++)
#pragma unroll
            for (int e = 0; e < NEXP; e++) {
                aA[e] += vAa[i] * wreg[i][e];
                aB[e] += vBa[i] * wreg[i][e];
            }

        float rA = butterfly8(aA, b0, b1, b2);
        float rB = butterfly8(aB, b0, b1, b2);

        int bufb = (pr & 1) * 2;
        if (lane < 8) {
            red[bufb][wid][myexp]     = rA;
            red[bufb + 1][wid][myexp] = rB;
        }
        __syncthreads();

        if (wid == 0 && lane < 16) {
            int which = lane >> 3, e = lane & 7;
            float s = bg[e];
#pragma unroll
            for (int w = 0; w < 8; w++) s += red[bufb + which][w][e];
            float m = s;
#pragma unroll
            for (int o = 4; o > 0; o >>= 1)
                m = fmaxf(m, __shfl_xor_sync(0xFFFFu, m, o, 8));
            float ex = __expf(s - m);
#pragma unroll
            for (int o = 4; o > 0; o >>= 1)
                ex += __shfl_xor_sync(0xFFFFu, ex, o, 8);
            if (e == 0) bestp[which ? tokB : tokA] = 1.0f / ex;
        }
    }
}

// ---------------- We transpose -> fp16 tiled+swizzled ----------------------
__global__ void __launch_bounds__(256)
convert_w_kernel(const float* __restrict__ We, __half* __restrict__ wt)
{
    __shared__ float tile[32][33];
    int bx = blockIdx.x, by = blockIdx.y;     // bx: n tile32, by: k tile32
    int tx = threadIdx.x & 31, ty = threadIdx.x >> 5;
    char* wtb = reinterpret_cast<char*>(wt);
#pragma unroll
    for (int j = 0; j < 4; j++)
        tile[ty + 8 * j][tx] = We[(size_t)(by * 32 + ty + 8 * j) * HDIM + bx * 32 + tx];
    __syncthreads();
#pragma unroll
    for (int j = 0; j < 4; j++) {
        int n = bx * 32 + ty + 8 * j;
        int k = by * 32 + tx;
        __half h = __float2half_rn(tile[tx][ty + 8 * j]);
        int bxt = n >> 7, row = n & 127, kc = k >> 6, colb = (k & 63) * 2;
        size_t off = ((size_t)(bxt * 16 + kc) << 14) +
                     (uint32_t)((row * 128 + colb) ^ ((row & 7) << 4));
        *reinterpret_cast<__half*>(wtb + off) = h;
    }
}

// ---------------- HMMA GEMM with cp.async.bulk feed ------------------------
#define BM 128
#define BN 128
#define BK 64
#define NCH (HDIM / BK)               // 16
#define STAGES 3
#define STAGE_BYTES (2 * TILE_BYTES)  // A tile + B tile = 32KB
#define SM_DATA 1024                  // stages start after mbar region
#define SMEM_TOTAL (SM_DATA + STAGES * STAGE_BYTES)   // 99328

__global__ void __launch_bounds__(256, 2)
moe_mma_kernel(const __half* __restrict__ xh,
               const __half* __restrict__ wt,
               const float* __restrict__ bias,
               const float* __restrict__ p,
               float* __restrict__ C)
{
    extern __shared__ char smem[];
    uint32_t sb = smem_u32(smem);
    int tid = threadIdx.x, lane = tid & 31, wid = tid >> 5;
    int wm = wid & 1, wn = wid >> 1;          // warp grid 2 x 4
    int bx = blockIdx.x, by = blockIdx.y;

    const char* asrc = reinterpret_cast<const char*>(xh) +
                       ((size_t)(by * NCH) << 14);
    const char* bsrc = reinterpret_cast<const char*>(wt) +
                       ((size_t)(bx * NCH) << 14);

    if (tid == 0) {
#pragma unroll
        for (int s = 0; s < STAGES; s++) MBARRIER_INIT(sb + s * 8, 1);
    }
    __syncthreads();

    float acc[4][4][4];
#pragma unroll
    for (int i = 0; i < 4; i++)
#pragma unroll
        for (int j = 0; j < 4; j++)
#pragma unroll
            for (int r = 0; r < 4; r++) acc[i][j][r] = 0.f;

    // prologue: load chunks 0..2 into stages 0..2
#pragma unroll
    for (int s = 0; s < STAGES; s++) {
        uint32_t stage = sb + SM_DATA + s * STAGE_BYTES;
        if (tid == 0) {
            MBARRIER_EXPECT_TX(sb + s * 8, STAGE_BYTES);
            bulk_g2s(stage, asrc + (size_t)s * TILE_BYTES, TILE_BYTES, sb + s * 8);
        }
        if (tid == 1)
            bulk_g2s(stage + TILE_BYTES, bsrc + (size_t)s * TILE_BYTES,
                     TILE_BYTES, sb + s * 8);
    }

    // per-lane ldmatrix addressing (swizzled layout, 128B rows)
    uint32_t xorv = (uint32_t)((lane & 7) << 4);
    uint32_t a_row = (uint32_t)(wm * 64 + (lane & 15));
    uint32_t a_chunk = (uint32_t)((lane >> 4) * 16);
    uint32_t b_row = (uint32_t)(wn * 32 + ((lane >> 4) & 1) * 8 + (lane & 7));
    uint32_t b_chunk = (uint32_t)(((lane >> 3) & 1) * 16);

    int use0 = 0, use1 = 0, use2 = 0;
    for (int c = 0; c < NCH; c++) {
        int s = c % 3;
        uint32_t mbar = sb + s * 8;
        int par = (s == 0 ? use0 : (s == 1 ? use1 : use2)) & 1;
        MBARRIER_WAIT_PARITY(mbar, par);
        if (s == 0) use0++; else if (s == 1) use1++; else use2++;

        uint32_t stageA = sb + SM_DATA + s * STAGE_BYTES;
        uint32_t stageB = stageA + TILE_BYTES;

#pragma unroll
        for (int ks = 0; ks < 4; ks++) {      // 4 K16 steps per BK=64
            uint32_t af[4][4], bf[2][4];
#pragma unroll
            for (int mi = 0; mi < 4; mi++)
                ldmatrix_x4(af[mi], stageA + (a_row + mi * 16) * 128 +
                                    ((a_chunk + ks * 32) ^ xorv));
#pragma unroll
            for (int np = 0; np < 2; np++)
                ldmatrix_x4(bf[np], stageB + (b_row + np * 16) * 128 +
                                    ((b_chunk + ks * 32) ^ xorv));
#pragma unroll
            for (int mi = 0; mi < 4; mi++) {
#pragma unroll
                for (int ni = 0; ni < 4; ni++)
                    mma_fp16(acc[mi][ni], af[mi], &bf[ni >> 1][(ni & 1) * 2]);
            }
        }

        __syncthreads();   // all warps done reading stage s

        if (c + 3 < NCH) {
            if (tid == 0) {
                MBARRIER_EXPECT_TX(mbar, STAGE_BYTES);
                bulk_g2s(stageA, asrc + (size_t)(c + 3) * TILE_BYTES,
                         TILE_BYTES, mbar);
            }
            if (tid == 1)
                bulk_g2s(stageB, bsrc + (size_t)(c + 3) * TILE_BYTES,
                         TILE_BYTES, mbar);
        }
    }

    // epilogue: (acc + bias) * p
    int m0 = by * BM + wm * 64;
    int n0 = bx * BN + wn * 32;
#pragma unroll
    for (int mi = 0; mi < 4; mi++) {
        int r0 = m0 + mi * 16 + (lane >> 2);
        int r1 = r0 + 8;
        float p0 = p[r0], p1 = p[r1];
#pragma unroll
        for (int ni = 0; ni < 4; ni++) {
            int n = n0 + ni * 8 + (lane & 3) * 2;
            float b0 = bias[n], b1 = bias[n + 1];
            float2 o0 = make_float2((acc[mi][ni][0] + b0) * p0,
                                    (acc[mi][ni][1] + b1) * p0);
            float2 o1 = make_float2((acc[mi][ni][2] + b0) * p1,
                                    (acc[mi][ni][3] + b1) * p1);
            *reinterpret_cast<float2*>(C + (size_t)r0 * HDIM + n) = o0;
            *reinterpret_cast<float2*>(C + (size_t)r1 * HDIM + n) = o1;
        }
    }
}

// ---------------- launch ----------------------------------------------------
extern "C" void kernel_launch(void* const* d_in, const int* in_sizes, int n_in,
                              void* d_out, int out_size)
{
    const float* x  = (const float*)d_in[0];
    const float* Wg = (const float*)d_in[1];
    const float* bg = (const float*)d_in[2];
    const float* We = (const float*)d_in[3];
    const float* be = (const float*)d_in[4];
    float* out = (float*)d_out;

    float* bestp;  cudaGetSymbolAddress((void**)&bestp, g_bestp);
    __half* xh;    cudaGetSymbolAddress((void**)&xh, g_xh);
    __half* wtp;   cudaGetSymbolAddress((void**)&wtp, g_wt);

    cudaFuncSetAttribute(moe_mma_kernel,
                         cudaFuncAttributeMaxDynamicSharedMemorySize, SMEM_TOTAL);

    prep_kernel<<<N_TOKENS / TPB, 256>>>(x, Wg, bg, xh, bestp);
    convert_w_kernel<<<dim3(32, 32), 256>>>(We, wtp);

    dim3 grid(HDIM / BN, N_TOKENS / BM);   // (8, 256)
    moe_mma_kernel<<<grid, 256, SMEM_TOTAL>>>(xh, wtp, be, bestp, out);
}